// round 4
// baseline (speedup 1.0000x reference)
#include <cuda_runtime.h>
#include <cstdint>

#define B_  2
#define T_  2048
#define D_  2048
#define H_  32
#define HD_ 64
#define SCALE_ 0.125f   // 1/sqrt(64)

// ---------------- scratch (device globals: allocation-free) ----------------
__device__ float g_q[(size_t)B_ * H_ * T_ * HD_];
__device__ float g_k[(size_t)B_ * H_ * T_ * HD_];
__device__ float g_v[(size_t)B_ * H_ * T_ * HD_];
__device__ float g_ctx[(size_t)B_ * T_ * D_];

// ---------------- helpers ----------------
__device__ __forceinline__ float to_tf32(float x) {
    uint32_t u;
    asm("cvt.rna.tf32.f32 %0, %1;" : "=r"(u) : "f"(x));
    return __uint_as_float(u);
}

__device__ __forceinline__ void mma8(float* c, const uint32_t* a, const uint32_t* b) {
    asm volatile(
        "mma.sync.aligned.m16n8k8.row.col.f32.tf32.tf32.f32 "
        "{%0,%1,%2,%3},{%4,%5,%6,%7},{%8,%9},{%0,%1,%2,%3};\n"
        : "+f"(c[0]), "+f"(c[1]), "+f"(c[2]), "+f"(c[3])
        : "r"(a[0]), "r"(a[1]), "r"(a[2]), "r"(a[3]), "r"(b[0]), "r"(b[1]));
}

// ============================================================================
// TF32 GEMM: C[M,N] = A[M,K] @ W[N,K]^T + bias
// MODE 0: C row-major [M,N]
// MODE 1: headed scatter: m=(b,t), n=(h,hd) -> C[((b*H+h)*T+t)*HD+hd]
// Block tile 128x128, K-tile 32, 8 warps (4x2), warp tile 32x64.
// ============================================================================
template <int MODE>
__global__ __launch_bounds__(256) void gemm_tf32(
    const float* __restrict__ A, const float* __restrict__ W,
    const float* __restrict__ bias, float* __restrict__ C,
    int M, int N, int K)
{
    __shared__ float As[128][36];
    __shared__ float Bs[128][36];

    const int tid  = threadIdx.x;
    const int m0   = blockIdx.y * 128;
    const int n0   = blockIdx.x * 128;
    const int warp = tid >> 5, lane = tid & 31;
    const int wm   = warp >> 1;       // 0..3
    const int wn   = warp & 1;        // 0..1
    const int gid  = lane >> 2;       // 0..7
    const int tig  = lane & 3;        // 0..3

    float acc[2][8][4];
#pragma unroll
    for (int i = 0; i < 2; i++)
#pragma unroll
        for (int j = 0; j < 8; j++)
#pragma unroll
            for (int r = 0; r < 4; r++) acc[i][j][r] = 0.f;

    const int lr = tid >> 3;          // 0..31
    const int lc = (tid & 7) << 2;    // 0,4,...,28

    for (int k0 = 0; k0 < K; k0 += 32) {
#pragma unroll
        for (int p = 0; p < 4; ++p) {
            int r = lr + p * 32;
            float4 va = *(const float4*)(A + (size_t)(m0 + r) * K + k0 + lc);
            float4 vb = *(const float4*)(W + (size_t)(n0 + r) * K + k0 + lc);
            va.x = to_tf32(va.x); va.y = to_tf32(va.y);
            va.z = to_tf32(va.z); va.w = to_tf32(va.w);
            vb.x = to_tf32(vb.x); vb.y = to_tf32(vb.y);
            vb.z = to_tf32(vb.z); vb.w = to_tf32(vb.w);
            *(float4*)&As[r][lc] = va;
            *(float4*)&Bs[r][lc] = vb;
        }
        __syncthreads();

#pragma unroll
        for (int ks = 0; ks < 4; ++ks) {
            const int k = ks * 8;
            uint32_t af[2][4];
#pragma unroll
            for (int mf = 0; mf < 2; ++mf) {
                int r = wm * 32 + mf * 16;
                af[mf][0] = __float_as_uint(As[r + gid    ][k + tig    ]);
                af[mf][1] = __float_as_uint(As[r + gid + 8][k + tig    ]);
                af[mf][2] = __float_as_uint(As[r + gid    ][k + tig + 4]);
                af[mf][3] = __float_as_uint(As[r + gid + 8][k + tig + 4]);
            }
            uint32_t bf[8][2];
#pragma unroll
            for (int nf = 0; nf < 8; ++nf) {
                int c = wn * 64 + nf * 8;
                bf[nf][0] = __float_as_uint(Bs[c + gid][k + tig    ]);
                bf[nf][1] = __float_as_uint(Bs[c + gid][k + tig + 4]);
            }
#pragma unroll
            for (int mf = 0; mf < 2; ++mf)
#pragma unroll
                for (int nf = 0; nf < 8; ++nf)
                    mma8(acc[mf][nf], af[mf], bf[nf]);
        }
        __syncthreads();
    }

    // epilogue
#pragma unroll
    for (int mf = 0; mf < 2; ++mf) {
#pragma unroll
        for (int nf = 0; nf < 8; ++nf) {
            int col  = n0 + wn * 64 + nf * 8 + tig * 2;
            float b0 = bias[col], b1 = bias[col + 1];
            int row0 = m0 + wm * 32 + mf * 16 + gid;
            float2 v0 = make_float2(acc[mf][nf][0] + b0, acc[mf][nf][1] + b1);
            float2 v1 = make_float2(acc[mf][nf][2] + b0, acc[mf][nf][3] + b1);
            if (MODE == 0) {
                *(float2*)(C + (size_t)row0 * N + col)       = v0;
                *(float2*)(C + (size_t)(row0 + 8) * N + col) = v1;
            } else {
                // m = b*T + t ; n = h*HD + hd  ->  ((b*H+h)*T+t)*HD + hd
                int b  = row0 >> 11;
                int hh = col >> 6;
                size_t i0 = (((size_t)b * H_ + hh) * T_ + (row0 & 2047)) * HD_ + (col & 63);
                size_t i1 = (((size_t)b * H_ + hh) * T_ + ((row0 + 8) & 2047)) * HD_ + (col & 63);
                *(float2*)(C + i0) = v0;
                *(float2*)(C + i1) = v1;
            }
        }
    }
}

// ============================================================================
// Causal flash attention, TF32 mma for S=Q@K^T and O=P@V.
// Grid: (T/64, B*H). Block: 128 threads (4 warps). Br=64, Bc=32, HD=64.
// Q,K,V layout: [B,H,T,HD]. Output ctx layout: [B,T,D].
// ============================================================================
__global__ __launch_bounds__(128) void attn_flash(
    const float* __restrict__ Q, const float* __restrict__ K,
    const float* __restrict__ V, float* __restrict__ ctx)
{
    __shared__ float Qs[64][68];   // [q][hd]
    __shared__ float Ks[32][68];   // [kv][hd]
    __shared__ float Vs[64][36];   // [hd][kv]  (transposed)
    __shared__ float Ss[64][36];   // [q][kv]   S then P
    __shared__ float mrow[64], lrow[64], frow[64];

    const int tid  = threadIdx.x;
    const int warp = tid >> 5, lane = tid & 31;
    const int gid  = lane >> 2, tig = lane & 3;
    const int qt   = blockIdx.x;       // query tile (64 rows)
    const int bh   = blockIdx.y;       // b*H + h

    const float* Qg = Q + (size_t)bh * T_ * HD_ + (size_t)qt * 64 * HD_;
    const float* Kg = K + (size_t)bh * T_ * HD_;
    const float* Vg = V + (size_t)bh * T_ * HD_;

    // load Q tile (tf32-rounded)
    {
        int r = tid >> 1, c0 = (tid & 1) * 32;
#pragma unroll
        for (int i = 0; i < 8; ++i) {
            float4 v = *(const float4*)(Qg + (size_t)r * HD_ + c0 + i * 4);
            v.x = to_tf32(v.x); v.y = to_tf32(v.y);
            v.z = to_tf32(v.z); v.w = to_tf32(v.w);
            *(float4*)&Qs[r][c0 + i * 4] = v;
        }
    }
    if (tid < 64) { mrow[tid] = -1e30f; lrow[tid] = 0.f; }

    float oacc[8][4];
#pragma unroll
    for (int i = 0; i < 8; i++)
#pragma unroll
        for (int j = 0; j < 4; j++) oacc[i][j] = 0.f;

    const int nkv = 2 * qt + 2;    // kv tiles of 32 up through the diagonal
    __syncthreads();

    for (int t = 0; t < nkv; ++t) {
        // ---- load K (direct) and V (transposed) tiles ----
        {
            int r = tid >> 2, c0 = (tid & 3) * 16;
#pragma unroll
            for (int i = 0; i < 4; ++i) {
                float4 kv = *(const float4*)(Kg + (size_t)(t * 32 + r) * HD_ + c0 + i * 4);
                kv.x = to_tf32(kv.x); kv.y = to_tf32(kv.y);
                kv.z = to_tf32(kv.z); kv.w = to_tf32(kv.w);
                *(float4*)&Ks[r][c0 + i * 4] = kv;
                float4 vv = *(const float4*)(Vg + (size_t)(t * 32 + r) * HD_ + c0 + i * 4);
                Vs[c0 + i * 4 + 0][r] = to_tf32(vv.x);
                Vs[c0 + i * 4 + 1][r] = to_tf32(vv.y);
                Vs[c0 + i * 4 + 2][r] = to_tf32(vv.z);
                Vs[c0 + i * 4 + 3][r] = to_tf32(vv.w);
            }
        }
        __syncthreads();

        // ---- S = Q @ K^T  (warp rows [warp*16, +16), cols 0..31) ----
        float sacc[4][4];
#pragma unroll
        for (int i = 0; i < 4; i++)
#pragma unroll
            for (int j = 0; j < 4; j++) sacc[i][j] = 0.f;

#pragma unroll
        for (int ks = 0; ks < 8; ++ks) {
            const int k = ks * 8;
            uint32_t af[4];
            int r = warp * 16;
            af[0] = __float_as_uint(Qs[r + gid    ][k + tig    ]);
            af[1] = __float_as_uint(Qs[r + gid + 8][k + tig    ]);
            af[2] = __float_as_uint(Qs[r + gid    ][k + tig + 4]);
            af[3] = __float_as_uint(Qs[r + gid + 8][k + tig + 4]);
            uint32_t bf[4][2];
#pragma unroll
            for (int nf = 0; nf < 4; ++nf) {
                int c = nf * 8;
                bf[nf][0] = __float_as_uint(Ks[c + gid][k + tig    ]);
                bf[nf][1] = __float_as_uint(Ks[c + gid][k + tig + 4]);
            }
#pragma unroll
            for (int nf = 0; nf < 4; ++nf) mma8(sacc[nf], af, bf[nf]);
        }
        // dump S tile to shared
#pragma unroll
        for (int nf = 0; nf < 4; ++nf) {
            int col = nf * 8 + tig * 2;
            int row = warp * 16 + gid;
            Ss[row    ][col    ] = sacc[nf][0];
            Ss[row    ][col + 1] = sacc[nf][1];
            Ss[row + 8][col    ] = sacc[nf][2];
            Ss[row + 8][col + 1] = sacc[nf][3];
        }
        __syncthreads();

        // ---- online softmax (one thread per row; rotated column order) ----
        if (tid < 64) {
            const int r    = tid;
            const int grow = qt * 64 + r;
            float vbuf[32];
            float mx = -1e30f;
#pragma unroll
            for (int j = 0; j < 32; ++j) {
                int c  = (j + r) & 31;
                int gc = t * 32 + c;
                float x = Ss[r][c] * SCALE_;
                if (gc > grow) x = -1e30f;
                vbuf[j] = x;
                mx = fmaxf(mx, x);
            }
            float mold = mrow[r];
            float mnew = fmaxf(mold, mx);
            float s = 0.f;
#pragma unroll
            for (int j = 0; j < 32; ++j) {
                float p = __expf(vbuf[j] - mnew);
                s += p;
                Ss[r][(j + r) & 31] = to_tf32(p);
            }
            float f = __expf(mold - mnew);
            frow[r] = f;
            mrow[r] = mnew;
            lrow[r] = lrow[r] * f + s;
        }
        __syncthreads();

        // ---- rescale O, then O += P @ V ----
        {
            float f0 = frow[warp * 16 + gid];
            float f8 = frow[warp * 16 + gid + 8];
#pragma unroll
            for (int nf = 0; nf < 8; ++nf) {
                oacc[nf][0] *= f0; oacc[nf][1] *= f0;
                oacc[nf][2] *= f8; oacc[nf][3] *= f8;
            }
        }
#pragma unroll
        for (int ks = 0; ks < 4; ++ks) {
            const int k = ks * 8;
            uint32_t af[4];
            int r = warp * 16;
            af[0] = __float_as_uint(Ss[r + gid    ][k + tig    ]);
            af[1] = __float_as_uint(Ss[r + gid + 8][k + tig    ]);
            af[2] = __float_as_uint(Ss[r + gid    ][k + tig + 4]);
            af[3] = __float_as_uint(Ss[r + gid + 8][k + tig + 4]);
            uint32_t bf[8][2];
#pragma unroll
            for (int nf = 0; nf < 8; ++nf) {
                int c = nf * 8;
                bf[nf][0] = __float_as_uint(Vs[c + gid][k + tig    ]);
                bf[nf][1] = __float_as_uint(Vs[c + gid][k + tig + 4]);
            }
#pragma unroll
            for (int nf = 0; nf < 8; ++nf) mma8(oacc[nf], af, bf[nf]);
        }
        __syncthreads();
    }

    // ---- write ctx [B,T,D] ----
    {
        int r0 = warp * 16 + gid;
        float il0 = 1.f / lrow[r0];
        float il8 = 1.f / lrow[r0 + 8];
        int b = bh >> 5, h = bh & 31;
        size_t base = ((size_t)b * T_ + (size_t)qt * 64) * D_ + h * 64;
#pragma unroll
        for (int nf = 0; nf < 8; ++nf) {
            int col = nf * 8 + tig * 2;
            float2 v0 = make_float2(oacc[nf][0] * il0, oacc[nf][1] * il0);
            float2 v1 = make_float2(oacc[nf][2] * il8, oacc[nf][3] * il8);
            *(float2*)(ctx + base + (size_t)r0 * D_ + col)       = v0;
            *(float2*)(ctx + base + (size_t)(r0 + 8) * D_ + col) = v1;
        }
    }
}

// ============================================================================
extern "C" void kernel_launch(void* const* d_in, const int* in_sizes, int n_in,
                              void* d_out, int out_size)
{
    (void)in_sizes; (void)n_in; (void)out_size;
    const float* X  = (const float*)d_in[0];
    const float* Wq = (const float*)d_in[1];
    const float* bq = (const float*)d_in[2];
    const float* Wk = (const float*)d_in[3];
    const float* bk = (const float*)d_in[4];
    const float* Wv = (const float*)d_in[5];
    const float* bv = (const float*)d_in[6];
    const float* Wo = (const float*)d_in[7];
    const float* bo = (const float*)d_in[8];
    float* out = (float*)d_out;

    float *q, *k, *v, *ctx;
    cudaGetSymbolAddress((void**)&q,   g_q);
    cudaGetSymbolAddress((void**)&k,   g_k);
    cudaGetSymbolAddress((void**)&v,   g_v);
    cudaGetSymbolAddress((void**)&ctx, g_ctx);

    const int M = B_ * T_;   // 4096
    const int N = D_;        // 2048
    const int K = D_;        // 2048
    dim3 gg(N / 128, M / 128);   // 16 x 32

    gemm_tf32<1><<<gg, 256>>>(X, Wq, bq, q, M, N, K);
    gemm_tf32<1><<<gg, 256>>>(X, Wk, bk, k, M, N, K);
    gemm_tf32<1><<<gg, 256>>>(X, Wv, bv, v, M, N, K);

    attn_flash<<<dim3(T_ / 64, B_ * H_), 128>>>(q, k, v, ctx);

    gemm_tf32<0><<<gg, 256>>>(ctx, Wo, bo, out, M, N, K);
}